// round 11
// baseline (speedup 1.0000x reference)
#include <cuda_runtime.h>

#define TPB 256
#define NB  5
#define TILE_FLOATS (TPB * NB)        // 1280
#define TILE_F4     (TILE_FLOATS / 4) // 320
#define NBLOCKS     888               // 148 SMs * 6 resident CTAs (forced by launch_bounds)

__device__ __forceinline__ float f_ex2(float x){ float y; asm("ex2.approx.ftz.f32 %0, %1;" : "=f"(y) : "f"(x)); return y; }
__device__ __forceinline__ float f_lg2(float x){ float y; asm("lg2.approx.ftz.f32 %0, %1;" : "=f"(y) : "f"(x)); return y; }
__device__ __forceinline__ float f_rcp(float x){ float y; asm("rcp.approx.ftz.f32 %0, %1;" : "=f"(y) : "f"(x)); return y; }
__device__ __forceinline__ float f_rsq(float x){ float y; asm("rsqrt.approx.ftz.f32 %0, %1;" : "=f"(y) : "f"(x)); return y; }

// Solve one row: q = W x + b, then KL-ball projection.
__device__ __forceinline__ void solve_row(const float* __restrict__ swb,
                                          const float xv[NB], float p[NB])
{
    const float LOG2_5 = 2.3219280948873623f;
    const float EPS2   = 0.14426950408889634f;   // 0.1 / ln2
    const float LN2    = 0.6931471805599453f;

    float q[NB];
    float S = 0.f, Q2 = 0.f;
    #pragma unroll
    for (int j = 0; j < NB; j++) {
        float4 wj = *reinterpret_cast<const float4*>(&swb[j * 8]);
        float2 wb = *reinterpret_cast<const float2*>(&swb[j * 8 + 4]);
        float acc = wb.y;
        acc = fmaf(xv[0], wj.x, acc);
        acc = fmaf(xv[1], wj.y, acc);
        acc = fmaf(xv[2], wj.z, acc);
        acc = fmaf(xv[3], wj.w, acc);
        acc = fmaf(xv[4], wb.x, acc);
        q[j] = acc;
        S  += acc;
        Q2  = fmaf(acc, acc, Q2);
    }
    float rS = f_rcp(S);

    // Fast sufficient feasibility (Jensen): KL(p||u) <= ln(5*Q2/S^2); e^0.1 ~ 1.10517092
    if (5.0f * Q2 <= 1.1051709f * S * S) {
        #pragma unroll
        for (int j = 0; j < NB; j++) p[j] = q[j] * rS;
        return;
    }
    // Exact test (uncommon)
    float L[NB], A1 = 0.f;
    #pragma unroll
    for (int j = 0; j < NB; j++) { L[j] = f_lg2(q[j]); A1 = fmaf(L[j], q[j], A1); }
    float KL1 = fmaf(A1, rS, LOG2_5) - f_lg2(S);
    if (KL1 <= EPS2) {
        #pragma unroll
        for (int j = 0; j < NB; j++) p[j] = q[j] * rS;
        return;
    }
    // Newton on f(t) = KL2(t) - EPS2 (rare)
    float t = f_rsq(KL1 * 6.9314718055994531f);      // sqrt(EPS2/KL1)
    t = fminf(fmaxf(t, 1e-3f), 0.999f);
    #pragma unroll
    for (int it = 0; it < 5; ++it) {
        float Se = 0.f, A = 0.f, B = 0.f;
        #pragma unroll
        for (int j = 0; j < NB; j++) {
            float z  = t * L[j];
            float e  = f_ex2(z);
            float ze = z * e;
            Se += e;  A += ze;  B = fmaf(z, ze, B);
        }
        float rSe   = f_rcp(Se);
        float fval  = fmaf(A, rSe, LOG2_5 - EPS2) - f_lg2(Se);
        float denom = LN2 * rSe * (B - A * A * rSe);
        t = t - fval * t * f_rcp(denom);
        t = fminf(fmaxf(t, 1e-4f), 1.0f);
    }
    float Se = 0.f, e[NB];
    #pragma unroll
    for (int j = 0; j < NB; j++) { e[j] = f_ex2(t * L[j]); Se += e[j]; }
    float rSe = f_rcp(Se);
    #pragma unroll
    for (int j = 0; j < NB; j++) p[j] = e[j] * rSe;
}

__global__ __launch_bounds__(TPB, 6)
void klproj_kernel(const float* __restrict__ x,
                   const float* __restrict__ W,
                   const float* __restrict__ b,
                   float* __restrict__ out,
                   int nrows, int ntiles)
{
    __shared__ float sin_[2][TILE_FLOATS];   // double-buffered input staging (10KB)
    __shared__ float swb[48];                // W rows padded to 8: [Wj0..Wj4, bj, -, -]

    const int tid   = threadIdx.x;
    const int total = nrows * NB;
    const bool has2 = tid < (TILE_F4 - TPB); // 320-256 = 64 extra float4 lanes

    if (tid < 48) {
        int j = tid >> 3, k = tid & 7;
        float v = 0.f;
        if (k < 5)       v = W[j * 5 + k];
        else if (k == 5) v = b[j];
        swb[tid] = v;
    }

    // ---- prologue: load first tile into registers ----
    int t = blockIdx.x;
    float4 r0, r1;
    {
        bool full0 = (t < ntiles) && ((t * TILE_FLOATS + TILE_FLOATS) <= total);
        if (full0) {
            const float4* g4 = reinterpret_cast<const float4*>(x) + (size_t)t * TILE_F4;
            r0 = g4[tid];
            if (has2) r1 = g4[tid + TPB];
        }
    }

    int buf = 0;
    for (; t < ntiles; t += NBLOCKS, buf ^= 1) {
        const int  fbase = t * TILE_FLOATS;
        const bool full  = (fbase + TILE_FLOATS) <= total;
        const int  tn    = t + NBLOCKS;
        const bool pfn   = (tn < ntiles) && ((tn * TILE_FLOATS + TILE_FLOATS) <= total);

        // stage current tile (already in regs) into buffer `buf`
        if (full) {
            float4* s4 = reinterpret_cast<float4*>(sin_[buf]);
            s4[tid] = r0;
            if (has2) s4[tid + TPB] = r1;
        }
        __syncthreads();   // the only barrier per tile (also covers swb on iter 0)

        // immediately issue next tile's loads: latency overlaps compute+stores below
        if (pfn) {
            const float4* g4 = reinterpret_cast<const float4*>(x) + (size_t)tn * TILE_F4;
            r0 = g4[tid];
            if (has2) r1 = g4[tid + TPB];
        }

        const int row = fbase / NB + tid;
        if (full) {
            float xv[NB], p[NB];
            #pragma unroll
            for (int j = 0; j < NB; j++) xv[j] = sin_[buf][tid * NB + j];  // stride-5: conflict-free
            solve_row(swb, xv, p);
            float* orow = out + (size_t)row * NB;
            #pragma unroll
            for (int j = 0; j < NB; j++) orow[j] = p[j];
        } else if (row < nrows) {
            float xv[NB], p[NB];
            #pragma unroll
            for (int j = 0; j < NB; j++) xv[j] = x[(size_t)row * NB + j];
            solve_row(swb, xv, p);
            float* orow = out + (size_t)row * NB;
            #pragma unroll
            for (int j = 0; j < NB; j++) orow[j] = p[j];
        }
        // no second barrier: next iteration writes the OTHER buffer; its own
        // __syncthreads() orders those STS against this iteration's LDS.
    }
}

extern "C" void kernel_launch(void* const* d_in, const int* in_sizes, int n_in,
                              void* d_out, int out_size)
{
    const float* x = (const float*)d_in[0];
    const float* W = (const float*)d_in[1];
    const float* b = (const float*)d_in[2];
    if (n_in >= 3 && in_sizes[1] == NB && in_sizes[2] == NB * NB) {
        const float* tmp = W; W = b; b = tmp;
    }
    float* out = (float*)d_out;
    int nrows  = in_sizes[0] / NB;
    int ntiles = (nrows + TPB - 1) / TPB;
    int blocks = (ntiles < NBLOCKS) ? ntiles : NBLOCKS;
    klproj_kernel<<<blocks, TPB>>>(x, W, b, out, nrows, ntiles);
}

// round 17
// speedup vs baseline: 1.0135x; 1.0135x over previous
#include <cuda_runtime.h>
#include <cstdint>

#define TPB 256
#define NB  5
#define WARPS_PER_CTA (TPB / 32)          // 8
#define ROWS_PER_WARP 32
#define TILE_FLOATS   (ROWS_PER_WARP * NB) // 160 floats = 40 float4 per warp-tile

__device__ __forceinline__ float f_ex2(float x){ float y; asm("ex2.approx.ftz.f32 %0, %1;" : "=f"(y) : "f"(x)); return y; }
__device__ __forceinline__ float f_lg2(float x){ float y; asm("lg2.approx.ftz.f32 %0, %1;" : "=f"(y) : "f"(x)); return y; }
__device__ __forceinline__ float f_rcp(float x){ float y; asm("rcp.approx.ftz.f32 %0, %1;" : "=f"(y) : "f"(x)); return y; }
__device__ __forceinline__ float f_rsq(float x){ float y; asm("rsqrt.approx.ftz.f32 %0, %1;" : "=f"(y) : "f"(x)); return y; }

__device__ __forceinline__ unsigned smem_u32(const void* p) {
    unsigned a;
    asm("{ .reg .u64 t; cvta.to.shared.u64 t, %1; cvt.u32.u64 %0, t; }" : "=r"(a) : "l"(p));
    return a;
}
__device__ __forceinline__ void cp_async16(unsigned s, const void* g) {
    asm volatile("cp.async.cg.shared.global [%0], [%1], 16;" :: "r"(s), "l"(g));
}
__device__ __forceinline__ void cp_async_wait_all() {
    asm volatile("cp.async.commit_group;\n\tcp.async.wait_group 0;" ::: "memory");
}

// q = W x + b, then KL-ball projection (Jensen fast path; exact+Newton fallback).
__device__ __forceinline__ void solve_row(const float* __restrict__ swb,
                                          const float xv[NB], float p[NB])
{
    const float LOG2_5 = 2.3219280948873623f;
    const float EPS2   = 0.14426950408889634f;   // 0.1 / ln2
    const float LN2    = 0.6931471805599453f;

    float q[NB];
    float S = 0.f, Q2 = 0.f;
    #pragma unroll
    for (int j = 0; j < NB; j++) {
        float4 wj = *reinterpret_cast<const float4*>(&swb[j * 8]);
        float2 wb = *reinterpret_cast<const float2*>(&swb[j * 8 + 4]);
        float acc = wb.y;
        acc = fmaf(xv[0], wj.x, acc);
        acc = fmaf(xv[1], wj.y, acc);
        acc = fmaf(xv[2], wj.z, acc);
        acc = fmaf(xv[3], wj.w, acc);
        acc = fmaf(xv[4], wb.x, acc);
        q[j] = acc;
        S  += acc;
        Q2  = fmaf(acc, acc, Q2);
    }
    float rS = f_rcp(S);

    // Sufficient feasibility (Jensen): KL(p||u) <= ln(5*Q2/S^2); e^0.1 ~ 1.10517092
    if (5.0f * Q2 <= 1.1051709f * S * S) {
        #pragma unroll
        for (int j = 0; j < NB; j++) p[j] = q[j] * rS;
        return;
    }
    float L[NB], A1 = 0.f;
    #pragma unroll
    for (int j = 0; j < NB; j++) { L[j] = f_lg2(q[j]); A1 = fmaf(L[j], q[j], A1); }
    float KL1 = fmaf(A1, rS, LOG2_5) - f_lg2(S);
    if (KL1 <= EPS2) {
        #pragma unroll
        for (int j = 0; j < NB; j++) p[j] = q[j] * rS;
        return;
    }
    float t = f_rsq(KL1 * 6.9314718055994531f);      // sqrt(EPS2/KL1)
    t = fminf(fmaxf(t, 1e-3f), 0.999f);
    #pragma unroll
    for (int it = 0; it < 5; ++it) {
        float Se = 0.f, A = 0.f, B = 0.f;
        #pragma unroll
        for (int j = 0; j < NB; j++) {
            float z  = t * L[j];
            float e  = f_ex2(z);
            float ze = z * e;
            Se += e;  A += ze;  B = fmaf(z, ze, B);
        }
        float rSe   = f_rcp(Se);
        float fval  = fmaf(A, rSe, LOG2_5 - EPS2) - f_lg2(Se);
        float denom = LN2 * rSe * (B - A * A * rSe);
        t = t - fval * t * f_rcp(denom);
        t = fminf(fmaxf(t, 1e-4f), 1.0f);
    }
    float Se = 0.f, e[NB];
    #pragma unroll
    for (int j = 0; j < NB; j++) { e[j] = f_ex2(t * L[j]); Se += e[j]; }
    float rSe = f_rcp(Se);
    #pragma unroll
    for (int j = 0; j < NB; j++) p[j] = e[j] * rSe;
}

__global__ __launch_bounds__(TPB)
void klproj_kernel(const float* __restrict__ x,
                   const float* __restrict__ W,
                   const float* __restrict__ b,
                   float* __restrict__ out,
                   int nrows)
{
    __shared__ float swb[48];                               // padded W rows: [Wj0..Wj4, bj, -, -]
    __shared__ float sin_[WARPS_PER_CTA][TILE_FLOATS];      // per-warp input (5KB)
    __shared__ float sout[WARPS_PER_CTA][TILE_FLOATS];      // per-warp output (5KB)

    const int tid  = threadIdx.x;
    const int wid  = tid >> 5;
    const int lane = tid & 31;

    if (tid < 48) {
        int j = tid >> 3, k = tid & 7;
        float v = 0.f;
        if (k < 5)       v = W[j * 5 + k];
        else if (k == 5) v = b[j];
        swb[tid] = v;
    }
    __syncthreads();   // one-time publish of swb; NO barriers after this

    const int tile    = blockIdx.x * WARPS_PER_CTA + wid;   // 32-row warp-tile
    const int rowbase = tile * ROWS_PER_WARP;
    if (rowbase >= nrows) return;
    const bool full = (rowbase + ROWS_PER_WARP) <= nrows;

    float xv[NB], p[NB];

    if (full) {
        // ---- warp-private staging via cp.async (no register round-trip) ----
        const float4* g4 = reinterpret_cast<const float4*>(x) + (size_t)tile * (TILE_FLOATS / 4);
        unsigned sbase = smem_u32(&sin_[wid][0]);
        cp_async16(sbase + (unsigned)lane * 16u, g4 + lane);
        if (lane < 8) cp_async16(sbase + (unsigned)(32 + lane) * 16u, g4 + 32 + lane);
        cp_async_wait_all();
        __syncwarp();

        #pragma unroll
        for (int j = 0; j < NB; j++) xv[j] = sin_[wid][lane * NB + j];  // stride-5: conflict-free
    } else {
        const int row = rowbase + lane;
        if (row < nrows) {
            #pragma unroll
            for (int j = 0; j < NB; j++) xv[j] = x[(size_t)row * NB + j];
        } else {
            #pragma unroll
            for (int j = 0; j < NB; j++) xv[j] = 1.0f;
        }
    }

    solve_row(swb, xv, p);

    if (full) {
        // ---- warp-private out staging -> coalesced STG.128 ----
        #pragma unroll
        for (int j = 0; j < NB; j++) sout[wid][lane * NB + j] = p[j];
        __syncwarp();
        const float4* s4 = reinterpret_cast<const float4*>(&sout[wid][0]);
        float4*       o4 = reinterpret_cast<float4*>(out) + (size_t)tile * (TILE_FLOATS / 4);
        o4[lane] = s4[lane];
        if (lane < 8) o4[32 + lane] = s4[32 + lane];
    } else {
        const int row = rowbase + lane;
        if (row < nrows) {
            float* orow = out + (size_t)row * NB;
            #pragma unroll
            for (int j = 0; j < NB; j++) orow[j] = p[j];
        }
    }
}

extern "C" void kernel_launch(void* const* d_in, const int* in_sizes, int n_in,
                              void* d_out, int out_size)
{
    const float* x = (const float*)d_in[0];
    const float* W = (const float*)d_in[1];
    const float* b = (const float*)d_in[2];
    if (n_in >= 3 && in_sizes[1] == NB && in_sizes[2] == NB * NB) {
        const float* tmp = W; W = b; b = tmp;
    }
    float* out = (float*)d_out;
    int nrows  = in_sizes[0] / NB;
    int ntiles = (nrows + ROWS_PER_WARP - 1) / ROWS_PER_WARP;
    int blocks = (ntiles + WARPS_PER_CTA - 1) / WARPS_PER_CTA;
    klproj_kernel<<<blocks, TPB>>>(x, W, b, out, nrows);
}